// round 15
// baseline (speedup 1.0000x reference)
#include <cuda_runtime.h>
#include <cuda_fp16.h>
#include <cstdint>

#define C 256
#define MAXN 100000
#define MAXE 3200000
#define KTOT 512
#define NCH  8192   // scan chunks
#define NPIPE 4     // spmm->gemm pipeline chunks

// Scratch (__device__ globals; allocation-free rule)
__device__ __align__(256) __half g_xh[(size_t)MAXN * C];    // fp16 x
__device__ __align__(256) __half g_axh[(size_t)MAXN * C];   // fp16 A@x
__device__ __align__(256) __half g_h0h[(size_t)MAXN * C];   // fp16 h0
__device__ __align__(256) __half g_Mth[C * KTOT];           // fp16 M^T [n][k]
__device__ int   g_cnt[MAXN];
__device__ int   g_rowstart[MAXN + 1];
__device__ int   g_cursor[MAXN];
__device__ __align__(16) uint2 g_colval[MAXE];              // interleaved CSR
__device__ int   g_psum[NCH];
__device__ int   g_poff[NCH];

// ---------------------------------------------------------------------------
// Inline edge-index dtype detection: int64 (little-endian, non-negative)
// => odd int32 words are zero high-halves. 16 broadcast loads, ~free.
// ---------------------------------------------------------------------------
__device__ __forceinline__ int detect_is64(const int* __restrict__ ei32) {
    int nz = 0;
    #pragma unroll
    for (int j = 1; j < 32; j += 2) nz |= __ldg(&ei32[j]);
    return nz == 0;
}

__global__ void zero_cnt_kernel(int N) {
    int i = blockIdx.x * blockDim.x + threadIdx.x;
    if (i < N) g_cnt[i] = 0;
}

// ---------------------------------------------------------------------------
// fp32 -> fp16 converters, 16 elements/thread
// ---------------------------------------------------------------------------
__device__ __forceinline__ uint4 pack8(float4 a, float4 b) {
    __half2 h0 = __floats2half2_rn(a.x, a.y);
    __half2 h1 = __floats2half2_rn(a.z, a.w);
    __half2 h2 = __floats2half2_rn(b.x, b.y);
    __half2 h3 = __floats2half2_rn(b.z, b.w);
    uint4 o;
    o.x = *reinterpret_cast<uint32_t*>(&h0);
    o.y = *reinterpret_cast<uint32_t*>(&h1);
    o.z = *reinterpret_cast<uint32_t*>(&h2);
    o.w = *reinterpret_cast<uint32_t*>(&h3);
    return o;
}

__global__ void cvt_x_kernel(const float* __restrict__ x, int total16) {
    int i = blockIdx.x * blockDim.x + threadIdx.x;
    if (i >= total16) return;
    const float4* p = reinterpret_cast<const float4*>(x) + (size_t)i * 4;
    float4 a = __ldg(p), b = __ldg(p + 1), c = __ldg(p + 2), d = __ldg(p + 3);
    uint4* dst = reinterpret_cast<uint4*>(g_xh) + (size_t)i * 2;
    dst[0] = pack8(a, b);
    dst[1] = pack8(c, d);
}

__global__ void cvt_h0_kernel(const float* __restrict__ h0, int total16) {
    int i = blockIdx.x * blockDim.x + threadIdx.x;
    if (i >= total16) return;
    const float4* p = reinterpret_cast<const float4*>(h0) + (size_t)i * 4;
    float4 a = __ldg(p), b = __ldg(p + 1), c = __ldg(p + 2), d = __ldg(p + 3);
    uint4* dst = reinterpret_cast<uint4*>(g_h0h) + (size_t)i * 2;
    dst[0] = pack8(a, b);
    dst[1] = pack8(c, d);
}

// Build transposed fp16 blend matrix g_Mth[n][k]
__global__ void build_Mt_kernel(const float* __restrict__ W1,
                                const float* __restrict__ W2,
                                const float* __restrict__ p_alpha,
                                const float* __restrict__ p_beta) {
    float a = *p_alpha, b = *p_beta;
    float c1 = (1.f - a) * (1.f - b);
    float c2 = (1.f - a) * b;
    float c3 = a * (1.f - b);
    float c4 = a * b;
    int i = blockIdx.x * blockDim.x + threadIdx.x;
    if (i >= C * KTOT) return;
    int n = i / KTOT, k = i % KTOT;
    float v;
    if (k < C) {
        v = c2 * W1[k * C + n] + (k == n ? c1 : 0.f);
    } else {
        int k2 = k - C;
        v = c4 * W2[k2 * C + n] + (k2 == n ? c3 : 0.f);
    }
    g_Mth[i] = __float2half_rn(v);
}

// ---------------------------------------------------------------------------
// CSR build: histogram (8-wide) -> 3-phase scan -> ticket scatter (2-wide)
// ---------------------------------------------------------------------------
__global__ void hist_kernel(const void* __restrict__ ei_raw, int E, int N) {
    const int is64 = detect_is64((const int*)ei_raw);
    const long long* ei64 = (const long long*)ei_raw;
    const int*       ei32 = (const int*)ei_raw;
    int base   = (blockIdx.x * blockDim.x + threadIdx.x) * 8;
    int stride = gridDim.x * blockDim.x * 8;
    for (int e = base; e + 8 <= E; e += stride) {
        int r[8];
        if (is64) {
            #pragma unroll
            for (int q = 0; q < 4; q++) {
                longlong2 p = __ldg(reinterpret_cast<const longlong2*>(
                                        &ei64[e + q * 2]));
                r[q * 2] = (int)p.x; r[q * 2 + 1] = (int)p.y;
            }
        } else {
            int4 p0 = __ldg(reinterpret_cast<const int4*>(&ei32[e]));
            int4 p1 = __ldg(reinterpret_cast<const int4*>(&ei32[e + 4]));
            r[0] = p0.x; r[1] = p0.y; r[2] = p0.z; r[3] = p0.w;
            r[4] = p1.x; r[5] = p1.y; r[6] = p1.z; r[7] = p1.w;
        }
        #pragma unroll
        for (int q = 0; q < 8; q++)
            if ((unsigned)r[q] < (unsigned)N) atomicAdd(&g_cnt[r[q]], 1);
    }
    if (base == 0) {
        for (int e = E & ~7; e < E; e++) {
            int rr = is64 ? (int)__ldg(&ei64[e]) : __ldg(&ei32[e]);
            if ((unsigned)rr < (unsigned)N) atomicAdd(&g_cnt[rr], 1);
        }
    }
}

__global__ void scan_p1(int N) {
    int j = blockIdx.x * blockDim.x + threadIdx.x;
    if (j >= NCH) return;
    int ch = (N + NCH - 1) / NCH;
    int s = j * ch, e = min(s + ch, N);
    int acc = 0;
    for (int i = s; i < e; i++) acc += g_cnt[i];
    g_psum[j] = acc;
}

__global__ void scan_p2() {
    __shared__ int sh[1024];
    int t = threadIdx.x;
    int loc[8];
    int s = 0;
    #pragma unroll
    for (int k = 0; k < 8; k++) { loc[k] = g_psum[t * 8 + k]; s += loc[k]; }
    sh[t] = s;
    __syncthreads();
    for (int off = 1; off < 1024; off <<= 1) {
        int add = (t >= off) ? sh[t - off] : 0;
        __syncthreads();
        sh[t] += add;
        __syncthreads();
    }
    int run = sh[t] - s;
    #pragma unroll
    for (int k = 0; k < 8; k++) { g_poff[t * 8 + k] = run; run += loc[k]; }
}

__global__ void scan_p3(int N, int E) {
    int j = blockIdx.x * blockDim.x + threadIdx.x;
    if (j >= NCH) return;
    int ch = (N + NCH - 1) / NCH;
    int s = j * ch, e = min(s + ch, N);
    int base = g_poff[j];
    for (int i = s; i < e; i++) {
        int c = g_cnt[i];
        g_rowstart[i] = base;
        g_cursor[i]   = base;
        base += c;
    }
    if (j == 0) g_rowstart[N] = E;
}

__global__ void scatter_kernel(const void* __restrict__ ei_raw,
                               const float* __restrict__ vals, int E, int N) {
    const int is64 = detect_is64((const int*)ei_raw);
    const long long* ei64 = (const long long*)ei_raw;
    const int*       ei32 = (const int*)ei_raw;
    int base   = (blockIdx.x * blockDim.x + threadIdx.x) * 2;
    int stride = gridDim.x * blockDim.x * 2;
    for (int e = base; e + 2 <= E; e += stride) {
        int row0, col0, row1, col1;
        if (is64) {
            longlong2 pr = __ldg(reinterpret_cast<const longlong2*>(&ei64[e]));
            longlong2 pc = __ldg(reinterpret_cast<const longlong2*>(
                                     &ei64[(size_t)E + e]));
            row0 = (int)pr.x; row1 = (int)pr.y;
            col0 = (int)pc.x; col1 = (int)pc.y;
        } else {
            int2 pr = __ldg(reinterpret_cast<const int2*>(&ei32[e]));
            int2 pc = __ldg(reinterpret_cast<const int2*>(&ei32[(size_t)E + e]));
            row0 = pr.x; row1 = pr.y;
            col0 = pc.x; col1 = pc.y;
        }
        float2 vv = __ldg(reinterpret_cast<const float2*>(&vals[e]));
        if ((unsigned)row0 < (unsigned)N && (unsigned)col0 < (unsigned)N) {
            int pos = atomicAdd(&g_cursor[row0], 1);
            __stcs(&g_colval[pos],
                   make_uint2((unsigned)col0, __float_as_uint(vv.x)));
        }
        if ((unsigned)row1 < (unsigned)N && (unsigned)col1 < (unsigned)N) {
            int pos = atomicAdd(&g_cursor[row1], 1);
            __stcs(&g_colval[pos],
                   make_uint2((unsigned)col1, __float_as_uint(vv.y)));
        }
    }
    if (base == 0 && (E & 1)) {
        int e = E - 1;
        int row = is64 ? (int)__ldg(&ei64[e]) : __ldg(&ei32[e]);
        int col = is64 ? (int)__ldg(&ei64[(size_t)E + e])
                       : __ldg(&ei32[(size_t)E + e]);
        if ((unsigned)row < (unsigned)N && (unsigned)col < (unsigned)N) {
            int pos = atomicAdd(&g_cursor[row], 1);
            __stcs(&g_colval[pos],
                   make_uint2((unsigned)col, __float_as_uint(__ldg(&vals[e]))));
        }
    }
}

// ---------------------------------------------------------------------------
// SpMM over CSR rows [rbase, rend): one warp per row; fp16 gathers.
// ---------------------------------------------------------------------------
__device__ __forceinline__ void accum8(float* acc, uint4 a, float v) {
    __half2* h = reinterpret_cast<__half2*>(&a);
    #pragma unroll
    for (int q = 0; q < 4; q++) {
        float2 f = __half22float2(h[q]);
        acc[2 * q]     += v * f.x;
        acc[2 * q + 1] += v * f.y;
    }
}

__global__ __launch_bounds__(256)
void spmm_csr_kernel(int rbase, int rend) {
    int warp = (blockIdx.x * blockDim.x + threadIdx.x) >> 5;
    int lane = threadIdx.x & 31;
    int nw   = (gridDim.x * blockDim.x) >> 5;
    for (int r = rbase + warp; r < rend; r += nw) {
        int s = g_rowstart[r];
        int e = g_rowstart[r + 1];
        float acc[8];
        #pragma unroll
        for (int q = 0; q < 8; q++) acc[q] = 0.f;
        int i = s;
        for (; i + 4 <= e; i += 4) {
            uint2 cv0 = __ldcs(&g_colval[i]);
            uint2 cv1 = __ldcs(&g_colval[i + 1]);
            uint2 cv2 = __ldcs(&g_colval[i + 2]);
            uint2 cv3 = __ldcs(&g_colval[i + 3]);
            uint4 a0 = __ldg(reinterpret_cast<const uint4*>(
                                 g_xh + (size_t)cv0.x * C) + lane);
            uint4 a1 = __ldg(reinterpret_cast<const uint4*>(
                                 g_xh + (size_t)cv1.x * C) + lane);
            uint4 a2 = __ldg(reinterpret_cast<const uint4*>(
                                 g_xh + (size_t)cv2.x * C) + lane);
            uint4 a3 = __ldg(reinterpret_cast<const uint4*>(
                                 g_xh + (size_t)cv3.x * C) + lane);
            accum8(acc, a0, __uint_as_float(cv0.y));
            accum8(acc, a1, __uint_as_float(cv1.y));
            accum8(acc, a2, __uint_as_float(cv2.y));
            accum8(acc, a3, __uint_as_float(cv3.y));
        }
        for (; i < e; i++) {
            uint2 cv0 = __ldcs(&g_colval[i]);
            uint4 a0 = __ldg(reinterpret_cast<const uint4*>(
                                 g_xh + (size_t)cv0.x * C) + lane);
            accum8(acc, a0, __uint_as_float(cv0.y));
        }
        __half2 q0 = __floats2half2_rn(acc[0], acc[1]);
        __half2 q1 = __floats2half2_rn(acc[2], acc[3]);
        __half2 q2 = __floats2half2_rn(acc[4], acc[5]);
        __half2 q3 = __floats2half2_rn(acc[6], acc[7]);
        uint4 o;
        o.x = *reinterpret_cast<uint32_t*>(&q0);
        o.y = *reinterpret_cast<uint32_t*>(&q1);
        o.z = *reinterpret_cast<uint32_t*>(&q2);
        o.w = *reinterpret_cast<uint32_t*>(&q3);
        __stcs(reinterpret_cast<uint4*>(g_axh + (size_t)r * C + lane * 8), o);
    }
}

// ---------------------------------------------------------------------------
// Single-term fp16 tensor-core GEMM over rows [rbase, rend):
//   out[rows,256] = [ax|h0] @ M (K=512). Tile 128x64, BK=32, 8 warps.
// ---------------------------------------------------------------------------
#define BM 128
#define BN 64
#define BK 32
#define LDS_W 20                          // words/row: 16 data + 4 pad
#define A_ARR_W (128 * LDS_W)             // 2560 words
#define B_ARR_W (64 * LDS_W)              // 1280 words
#define STG_W (A_ARR_W + B_ARR_W)         // 3840 words = 15360 B
#define SMEM_BYTES (2 * STG_W * 4)        // 30720 B

__device__ __forceinline__ uint32_t s2u(const void* p) {
    uint32_t a;
    asm("{ .reg .u64 t; cvta.to.shared.u64 t, %1; cvt.u32.u64 %0, t; }"
        : "=r"(a) : "l"(p));
    return a;
}
__device__ __forceinline__ void cp16(uint32_t daddr, const void* g) {
    asm volatile("cp.async.cg.shared.global [%0], [%1], 16;"
                 :: "r"(daddr), "l"(g));
}
__device__ __forceinline__ void cp16z(uint32_t daddr, const void* g) {
    asm volatile("cp.async.cg.shared.global [%0], [%1], 16, 0;"
                 :: "r"(daddr), "l"(g));
}
__device__ __forceinline__ void cp_commit() {
    asm volatile("cp.async.commit_group;");
}
__device__ __forceinline__ void cp_wait0() {
    asm volatile("cp.async.wait_group 0;");
}
__device__ __forceinline__ void ldm_x4(uint32_t* r, uint32_t addr) {
    asm volatile("ldmatrix.sync.aligned.m8n8.x4.shared.b16 {%0,%1,%2,%3}, [%4];"
                 : "=r"(r[0]), "=r"(r[1]), "=r"(r[2]), "=r"(r[3]) : "r"(addr));
}
__device__ __forceinline__ void mma_f16(float* c, const uint32_t* a,
                                        uint32_t b0, uint32_t b1) {
    asm volatile(
        "mma.sync.aligned.m16n8k16.row.col.f32.f16.f16.f32 "
        "{%0,%1,%2,%3}, {%4,%5,%6,%7}, {%8,%9}, {%0,%1,%2,%3};"
        : "+f"(c[0]), "+f"(c[1]), "+f"(c[2]), "+f"(c[3])
        : "r"(a[0]), "r"(a[1]), "r"(a[2]), "r"(a[3]), "r"(b0), "r"(b1));
}

__global__ __launch_bounds__(256, 3)
void gemm_f16_kernel(float* __restrict__ out, int rbase, int rend) {
    extern __shared__ uint32_t smem[];
    const uint32_t sbase = s2u(smem);

    const int tid  = threadIdx.x;
    const int lane = tid & 31;
    const int wid  = tid >> 5;
    const int warp_m = (wid & 3) * 32;
    const int warp_n = (wid >> 2) * 32;
    const int bn = blockIdx.x * BN;
    const int bm = rbase + blockIdx.y * BM;

    const int a_row = (lane & 7) + ((lane >> 3) & 1) * 8;
    const int a_k   = (lane >> 4) * 8;
    const int b_row = (lane & 7) + (lane >> 4) * 8;
    const int b_k   = ((lane >> 3) & 1) * 8;

    float acc[2][4][4];
    #pragma unroll
    for (int i = 0; i < 2; i++)
        #pragma unroll
        for (int j = 0; j < 4; j++)
            #pragma unroll
            for (int q = 0; q < 4; q++) acc[i][j][q] = 0.f;

    const int lrow = tid >> 1;
    const int lc   = tid & 1;
    const int arow = bm + lrow;
    const bool avalid = (arow < rend);
    const int acl = avalid ? arow : rbase;
    const int brow = tid >> 2;
    const int bq   = tid & 3;

    const int T = KTOT / BK;   // 16 tiles

    auto load_tile = [&](int t, int stg) {
        const int kt = t * BK;
        const size_t aoff = (size_t)acl * C + ((kt < C) ? kt : kt - C);
        const __half* gA = (kt < C) ? (g_axh + aoff) : (g_h0h + aoff);
        uint32_t drow = sbase + (stg * STG_W + lrow * LDS_W) * 4;
        #pragma unroll
        for (int c = 0; c < 2; c++) {
            int chunk = lc * 2 + c;
            if (avalid) cp16(drow + chunk * 16, gA + chunk * 8);
            else        cp16z(drow + chunk * 16, gA + chunk * 8);
        }
        const size_t boff = (size_t)(bn + brow) * KTOT + kt + bq * 8;
        uint32_t db = sbase + (stg * STG_W + A_ARR_W + brow * LDS_W) * 4 + bq * 16;
        cp16(db, g_Mth + boff);
        cp_commit();
    };

    load_tile(0, 0);

    for (int t = 0; t < T; t++) {
        cp_wait0();
        __syncthreads();
        if (t + 1 < T) load_tile(t + 1, (t + 1) & 1);

        const int stg = t & 1;
        const uint32_t aS0 = sbase + (stg * STG_W) * 4;
        const uint32_t bS0 = aS0 + A_ARR_W * 4;

        #pragma unroll
        for (int ks = 0; ks < 2; ks++) {
            const int kk = ks * 16;
            uint32_t aR[2][4];
            #pragma unroll
            for (int mt = 0; mt < 2; mt++) {
                uint32_t off = ((warp_m + mt * 16 + a_row) * LDS_W) * 4
                             + (kk + a_k) * 2;
                ldm_x4(aR[mt], aS0 + off);
            }
            #pragma unroll
            for (int ntp = 0; ntp < 2; ntp++) {
                uint32_t bR[4];
                uint32_t off = ((warp_n + ntp * 16 + b_row) * LDS_W) * 4
                             + (kk + b_k) * 2;
                ldm_x4(bR, bS0 + off);
                #pragma unroll
                for (int mt = 0; mt < 2; mt++) {
                    #pragma unroll
                    for (int j = 0; j < 2; j++) {
                        mma_f16(acc[mt][ntp * 2 + j], aR[mt],
                                bR[2 * j], bR[2 * j + 1]);
                    }
                }
            }
        }
        __syncthreads();
    }

    #pragma unroll
    for (int mt = 0; mt < 2; mt++) {
        #pragma unroll
        for (int nt = 0; nt < 4; nt++) {
            int r0  = bm + warp_m + mt * 16 + (lane >> 2);
            int col = bn + warp_n + nt * 8 + (lane & 3) * 2;
            if (r0 < rend)
                *reinterpret_cast<float2*>(out + (size_t)r0 * C + col) =
                    make_float2(acc[mt][nt][0], acc[mt][nt][1]);
            int r1 = r0 + 8;
            if (r1 < rend)
                *reinterpret_cast<float2*>(out + (size_t)r1 * C + col) =
                    make_float2(acc[mt][nt][2], acc[mt][nt][3]);
        }
    }
}

// ---------------------------------------------------------------------------
// Launch: prep || CSR-build fork, then chunked SpMM->GEMM pipeline
// (SpMM L2-bound on main, GEMM tensor-bound on side stream).
// ---------------------------------------------------------------------------
extern "C" void kernel_launch(void* const* d_in, const int* in_sizes, int n_in,
                              void* d_out, int out_size) {
    const float* x    = (const float*)d_in[0];
    const float* vals = (const float*)d_in[1];
    const void*  ei   = d_in[2];
    const float* h0   = (const float*)d_in[3];
    const float* W1   = (const float*)d_in[4];
    const float* W2   = (const float*)d_in[5];
    const float* pa   = (const float*)d_in[6];
    const float* pb   = (const float*)d_in[7];
    float* out = (float*)d_out;

    const int N = in_sizes[0] / C;     // 100000
    int E = in_sizes[1];               // 3200000
    if (E > MAXE) E = MAXE;

    static cudaStream_t s2 = nullptr;
    static cudaEvent_t evFork = nullptr, evJoin = nullptr, evEnd = nullptr;
    static cudaEvent_t evS[NPIPE] = {};
    if (s2 == nullptr) {
        cudaStreamCreateWithFlags(&s2, cudaStreamNonBlocking);
        cudaEventCreateWithFlags(&evFork, cudaEventDisableTiming);
        cudaEventCreateWithFlags(&evJoin, cudaEventDisableTiming);
        cudaEventCreateWithFlags(&evEnd, cudaEventDisableTiming);
        for (int i = 0; i < NPIPE; i++)
            cudaEventCreateWithFlags(&evS[i], cudaEventDisableTiming);
        cudaFuncSetAttribute(gemm_f16_kernel,
                             cudaFuncAttributeMaxDynamicSharedMemorySize,
                             SMEM_BYTES);
    }

    // fork
    cudaEventRecord(evFork, 0);
    cudaStreamWaitEvent(s2, evFork, 0);

    // side stream: DRAM-streaming prep (independent of edges)
    int total16 = N * C / 16;
    cvt_x_kernel<<<(total16 + 255) / 256, 256, 0, s2>>>(x, total16);
    cvt_h0_kernel<<<(total16 + 255) / 256, 256, 0, s2>>>(h0, total16);
    build_Mt_kernel<<<(C * KTOT + 255) / 256, 256, 0, s2>>>(W1, W2, pa, pb);
    cudaEventRecord(evJoin, s2);

    // main stream: CSR build (latency/atomic-bound, DRAM-idle)
    zero_cnt_kernel<<<(N + 255) / 256, 256>>>(N);
    hist_kernel<<<1563, 256>>>(ei, E, N);
    scan_p1<<<NCH / 256, 256>>>(N);
    scan_p2<<<1, 1024>>>();
    scan_p3<<<NCH / 256, 256>>>(N, E);
    scatter_kernel<<<3125, 256>>>(ei, vals, E, N);

    // join: SpMM needs cvt_x (side) + scatter (main)
    cudaStreamWaitEvent(0, evJoin, 0);

    // chunked SpMM (main) -> GEMM (side) pipeline
    const int chunkRows = (((N + NPIPE - 1) / NPIPE) + BM - 1) & ~(BM - 1);
    for (int c = 0; c < NPIPE; c++) {
        int rbase = c * chunkRows;
        if (rbase >= N) break;
        int rend = rbase + chunkRows;
        if (rend > N) rend = N;
        int rows = rend - rbase;
        int blocks = (rows * 32 + 255) / 256;
        spmm_csr_kernel<<<blocks, 256>>>(rbase, rend);
        cudaEventRecord(evS[c], 0);
        cudaStreamWaitEvent(s2, evS[c], 0);
        dim3 ggrid(C / BN, (rows + BM - 1) / BM);
        gemm_f16_kernel<<<ggrid, 256, SMEM_BYTES, s2>>>(out, rbase, rend);
    }

    // join side stream back so all work completes on capture stream
    cudaEventRecord(evEnd, s2);
    cudaStreamWaitEvent(0, evEnd, 0);
}

// round 16
// speedup vs baseline: 1.0780x; 1.0780x over previous
#include <cuda_runtime.h>
#include <cuda_fp16.h>
#include <cstdint>

#define C 256
#define MAXN 100000
#define MAXE 3200000
#define KTOT 512
#define NCH  8192   // scan chunks

// Scratch (__device__ globals; allocation-free rule)
__device__ __align__(256) __half g_xh[(size_t)MAXN * C];    // fp16 x
__device__ __align__(256) __half g_axh[(size_t)MAXN * C];   // fp16 A@x
__device__ __align__(256) __half g_h0h[(size_t)MAXN * C];   // fp16 h0
__device__ __align__(256) __half g_Mth[C * KTOT];           // fp16 M^T [n][k]
__device__ int   g_cnt[MAXN];
__device__ int   g_rowstart[MAXN + 1];
__device__ int   g_cursor[MAXN];
__device__ __align__(16) uint2 g_colval[MAXE];              // interleaved CSR
__device__ int   g_psum[NCH];
__device__ int   g_poff[NCH];

// ---------------------------------------------------------------------------
// Inline edge-index dtype detection: int64 (little-endian, non-negative)
// => odd int32 words are zero high-halves. 16 broadcast loads, ~free.
// ---------------------------------------------------------------------------
__device__ __forceinline__ int detect_is64(const int* __restrict__ ei32) {
    int nz = 0;
    #pragma unroll
    for (int j = 1; j < 32; j += 2) nz |= __ldg(&ei32[j]);
    return nz == 0;
}

__global__ void zero_cnt_kernel(int N) {
    int i = blockIdx.x * blockDim.x + threadIdx.x;
    if (i < N) g_cnt[i] = 0;
}

// ---------------------------------------------------------------------------
// fp32 -> fp16 converters, 16 elements/thread
// ---------------------------------------------------------------------------
__device__ __forceinline__ uint4 pack8(float4 a, float4 b) {
    __half2 h0 = __floats2half2_rn(a.x, a.y);
    __half2 h1 = __floats2half2_rn(a.z, a.w);
    __half2 h2 = __floats2half2_rn(b.x, b.y);
    __half2 h3 = __floats2half2_rn(b.z, b.w);
    uint4 o;
    o.x = *reinterpret_cast<uint32_t*>(&h0);
    o.y = *reinterpret_cast<uint32_t*>(&h1);
    o.z = *reinterpret_cast<uint32_t*>(&h2);
    o.w = *reinterpret_cast<uint32_t*>(&h3);
    return o;
}

__global__ void cvt_x_kernel(const float* __restrict__ x, int total16) {
    int i = blockIdx.x * blockDim.x + threadIdx.x;
    if (i >= total16) return;
    const float4* p = reinterpret_cast<const float4*>(x) + (size_t)i * 4;
    float4 a = __ldg(p), b = __ldg(p + 1), c = __ldg(p + 2), d = __ldg(p + 3);
    uint4* dst = reinterpret_cast<uint4*>(g_xh) + (size_t)i * 2;
    dst[0] = pack8(a, b);
    dst[1] = pack8(c, d);
}

__global__ void cvt_h0_kernel(const float* __restrict__ h0, int total16) {
    int i = blockIdx.x * blockDim.x + threadIdx.x;
    if (i >= total16) return;
    const float4* p = reinterpret_cast<const float4*>(h0) + (size_t)i * 4;
    float4 a = __ldg(p), b = __ldg(p + 1), c = __ldg(p + 2), d = __ldg(p + 3);
    uint4* dst = reinterpret_cast<uint4*>(g_h0h) + (size_t)i * 2;
    dst[0] = pack8(a, b);
    dst[1] = pack8(c, d);
}

// Build transposed fp16 blend matrix g_Mth[n][k]
__global__ void build_Mt_kernel(const float* __restrict__ W1,
                                const float* __restrict__ W2,
                                const float* __restrict__ p_alpha,
                                const float* __restrict__ p_beta) {
    float a = *p_alpha, b = *p_beta;
    float c1 = (1.f - a) * (1.f - b);
    float c2 = (1.f - a) * b;
    float c3 = a * (1.f - b);
    float c4 = a * b;
    int i = blockIdx.x * blockDim.x + threadIdx.x;
    if (i >= C * KTOT) return;
    int n = i / KTOT, k = i % KTOT;
    float v;
    if (k < C) {
        v = c2 * W1[k * C + n] + (k == n ? c1 : 0.f);
    } else {
        int k2 = k - C;
        v = c4 * W2[k2 * C + n] + (k2 == n ? c3 : 0.f);
    }
    g_Mth[i] = __float2half_rn(v);
}

// ---------------------------------------------------------------------------
// CSR build: histogram (8-wide) -> 3-phase scan -> ticket scatter (2-wide)
// ---------------------------------------------------------------------------
__global__ void hist_kernel(const void* __restrict__ ei_raw, int E, int N) {
    const int is64 = detect_is64((const int*)ei_raw);
    const long long* ei64 = (const long long*)ei_raw;
    const int*       ei32 = (const int*)ei_raw;
    int base   = (blockIdx.x * blockDim.x + threadIdx.x) * 8;
    int stride = gridDim.x * blockDim.x * 8;
    for (int e = base; e + 8 <= E; e += stride) {
        int r[8];
        if (is64) {
            #pragma unroll
            for (int q = 0; q < 4; q++) {
                longlong2 p = __ldg(reinterpret_cast<const longlong2*>(
                                        &ei64[e + q * 2]));
                r[q * 2] = (int)p.x; r[q * 2 + 1] = (int)p.y;
            }
        } else {
            int4 p0 = __ldg(reinterpret_cast<const int4*>(&ei32[e]));
            int4 p1 = __ldg(reinterpret_cast<const int4*>(&ei32[e + 4]));
            r[0] = p0.x; r[1] = p0.y; r[2] = p0.z; r[3] = p0.w;
            r[4] = p1.x; r[5] = p1.y; r[6] = p1.z; r[7] = p1.w;
        }
        #pragma unroll
        for (int q = 0; q < 8; q++)
            if ((unsigned)r[q] < (unsigned)N) atomicAdd(&g_cnt[r[q]], 1);
    }
    if (base == 0) {
        for (int e = E & ~7; e < E; e++) {
            int rr = is64 ? (int)__ldg(&ei64[e]) : __ldg(&ei32[e]);
            if ((unsigned)rr < (unsigned)N) atomicAdd(&g_cnt[rr], 1);
        }
    }
}

__global__ void scan_p1(int N) {
    int j = blockIdx.x * blockDim.x + threadIdx.x;
    if (j >= NCH) return;
    int ch = (N + NCH - 1) / NCH;
    int s = j * ch, e = min(s + ch, N);
    int acc = 0;
    for (int i = s; i < e; i++) acc += g_cnt[i];
    g_psum[j] = acc;
}

__global__ void scan_p2() {
    __shared__ int sh[1024];
    int t = threadIdx.x;
    int loc[8];
    int s = 0;
    #pragma unroll
    for (int k = 0; k < 8; k++) { loc[k] = g_psum[t * 8 + k]; s += loc[k]; }
    sh[t] = s;
    __syncthreads();
    for (int off = 1; off < 1024; off <<= 1) {
        int add = (t >= off) ? sh[t - off] : 0;
        __syncthreads();
        sh[t] += add;
        __syncthreads();
    }
    int run = sh[t] - s;
    #pragma unroll
    for (int k = 0; k < 8; k++) { g_poff[t * 8 + k] = run; run += loc[k]; }
}

__global__ void scan_p3(int N, int E) {
    int j = blockIdx.x * blockDim.x + threadIdx.x;
    if (j >= NCH) return;
    int ch = (N + NCH - 1) / NCH;
    int s = j * ch, e = min(s + ch, N);
    int base = g_poff[j];
    for (int i = s; i < e; i++) {
        int c = g_cnt[i];
        g_rowstart[i] = base;
        g_cursor[i]   = base;
        base += c;
    }
    if (j == 0) g_rowstart[N] = E;
}

__global__ void scatter_kernel(const void* __restrict__ ei_raw,
                               const float* __restrict__ vals, int E, int N) {
    const int is64 = detect_is64((const int*)ei_raw);
    const long long* ei64 = (const long long*)ei_raw;
    const int*       ei32 = (const int*)ei_raw;
    int base   = (blockIdx.x * blockDim.x + threadIdx.x) * 2;
    int stride = gridDim.x * blockDim.x * 2;
    for (int e = base; e + 2 <= E; e += stride) {
        int row0, col0, row1, col1;
        if (is64) {
            longlong2 pr = __ldg(reinterpret_cast<const longlong2*>(&ei64[e]));
            longlong2 pc = __ldg(reinterpret_cast<const longlong2*>(
                                     &ei64[(size_t)E + e]));
            row0 = (int)pr.x; row1 = (int)pr.y;
            col0 = (int)pc.x; col1 = (int)pc.y;
        } else {
            int2 pr = __ldg(reinterpret_cast<const int2*>(&ei32[e]));
            int2 pc = __ldg(reinterpret_cast<const int2*>(&ei32[(size_t)E + e]));
            row0 = pr.x; row1 = pr.y;
            col0 = pc.x; col1 = pc.y;
        }
        float2 vv = __ldg(reinterpret_cast<const float2*>(&vals[e]));
        if ((unsigned)row0 < (unsigned)N && (unsigned)col0 < (unsigned)N) {
            int pos = atomicAdd(&g_cursor[row0], 1);
            __stcs(&g_colval[pos],
                   make_uint2((unsigned)col0, __float_as_uint(vv.x)));
        }
        if ((unsigned)row1 < (unsigned)N && (unsigned)col1 < (unsigned)N) {
            int pos = atomicAdd(&g_cursor[row1], 1);
            __stcs(&g_colval[pos],
                   make_uint2((unsigned)col1, __float_as_uint(vv.y)));
        }
    }
    if (base == 0 && (E & 1)) {
        int e = E - 1;
        int row = is64 ? (int)__ldg(&ei64[e]) : __ldg(&ei32[e]);
        int col = is64 ? (int)__ldg(&ei64[(size_t)E + e])
                       : __ldg(&ei32[(size_t)E + e]);
        if ((unsigned)row < (unsigned)N && (unsigned)col < (unsigned)N) {
            int pos = atomicAdd(&g_cursor[row], 1);
            __stcs(&g_colval[pos],
                   make_uint2((unsigned)col, __float_as_uint(__ldg(&vals[e]))));
        }
    }
}

// ---------------------------------------------------------------------------
// SpMM over CSR (monolithic): one warp per row; fp16 gathers, 4-edge unroll.
// ---------------------------------------------------------------------------
__device__ __forceinline__ void accum8(float* acc, uint4 a, float v) {
    __half2* h = reinterpret_cast<__half2*>(&a);
    #pragma unroll
    for (int q = 0; q < 4; q++) {
        float2 f = __half22float2(h[q]);
        acc[2 * q]     += v * f.x;
        acc[2 * q + 1] += v * f.y;
    }
}

__global__ __launch_bounds__(256)
void spmm_csr_kernel(int N) {
    int warp = (blockIdx.x * blockDim.x + threadIdx.x) >> 5;
    int lane = threadIdx.x & 31;
    int nw   = (gridDim.x * blockDim.x) >> 5;
    for (int r = warp; r < N; r += nw) {
        int s = g_rowstart[r];
        int e = g_rowstart[r + 1];
        float acc[8];
        #pragma unroll
        for (int q = 0; q < 8; q++) acc[q] = 0.f;
        int i = s;
        for (; i + 4 <= e; i += 4) {
            uint2 cv0 = __ldcs(&g_colval[i]);
            uint2 cv1 = __ldcs(&g_colval[i + 1]);
            uint2 cv2 = __ldcs(&g_colval[i + 2]);
            uint2 cv3 = __ldcs(&g_colval[i + 3]);
            uint4 a0 = __ldg(reinterpret_cast<const uint4*>(
                                 g_xh + (size_t)cv0.x * C) + lane);
            uint4 a1 = __ldg(reinterpret_cast<const uint4*>(
                                 g_xh + (size_t)cv1.x * C) + lane);
            uint4 a2 = __ldg(reinterpret_cast<const uint4*>(
                                 g_xh + (size_t)cv2.x * C) + lane);
            uint4 a3 = __ldg(reinterpret_cast<const uint4*>(
                                 g_xh + (size_t)cv3.x * C) + lane);
            accum8(acc, a0, __uint_as_float(cv0.y));
            accum8(acc, a1, __uint_as_float(cv1.y));
            accum8(acc, a2, __uint_as_float(cv2.y));
            accum8(acc, a3, __uint_as_float(cv3.y));
        }
        for (; i < e; i++) {
            uint2 cv0 = __ldcs(&g_colval[i]);
            uint4 a0 = __ldg(reinterpret_cast<const uint4*>(
                                 g_xh + (size_t)cv0.x * C) + lane);
            accum8(acc, a0, __uint_as_float(cv0.y));
        }
        __half2 q0 = __floats2half2_rn(acc[0], acc[1]);
        __half2 q1 = __floats2half2_rn(acc[2], acc[3]);
        __half2 q2 = __floats2half2_rn(acc[4], acc[5]);
        __half2 q3 = __floats2half2_rn(acc[6], acc[7]);
        uint4 o;
        o.x = *reinterpret_cast<uint32_t*>(&q0);
        o.y = *reinterpret_cast<uint32_t*>(&q1);
        o.z = *reinterpret_cast<uint32_t*>(&q2);
        o.w = *reinterpret_cast<uint32_t*>(&q3);
        __stcs(reinterpret_cast<uint4*>(g_axh + (size_t)r * C + lane * 8), o);
    }
}

// ---------------------------------------------------------------------------
// Single-term fp16 tensor-core GEMM: out[N,256] = [ax|h0] @ M (K=512).
// Tile 128x64, BK=32, 8 warps of 32x32, fp32 accumulate.
// ---------------------------------------------------------------------------
#define BM 128
#define BN 64
#define BK 32
#define LDS_W 20                          // words/row: 16 data + 4 pad
#define A_ARR_W (128 * LDS_W)             // 2560 words
#define B_ARR_W (64 * LDS_W)              // 1280 words
#define STG_W (A_ARR_W + B_ARR_W)         // 3840 words = 15360 B
#define SMEM_BYTES (2 * STG_W * 4)        // 30720 B

__device__ __forceinline__ uint32_t s2u(const void* p) {
    uint32_t a;
    asm("{ .reg .u64 t; cvta.to.shared.u64 t, %1; cvt.u32.u64 %0, t; }"
        : "=r"(a) : "l"(p));
    return a;
}
__device__ __forceinline__ void cp16(uint32_t daddr, const void* g) {
    asm volatile("cp.async.cg.shared.global [%0], [%1], 16;"
                 :: "r"(daddr), "l"(g));
}
__device__ __forceinline__ void cp16z(uint32_t daddr, const void* g) {
    asm volatile("cp.async.cg.shared.global [%0], [%1], 16, 0;"
                 :: "r"(daddr), "l"(g));
}
__device__ __forceinline__ void cp_commit() {
    asm volatile("cp.async.commit_group;");
}
__device__ __forceinline__ void cp_wait0() {
    asm volatile("cp.async.wait_group 0;");
}
__device__ __forceinline__ void ldm_x4(uint32_t* r, uint32_t addr) {
    asm volatile("ldmatrix.sync.aligned.m8n8.x4.shared.b16 {%0,%1,%2,%3}, [%4];"
                 : "=r"(r[0]), "=r"(r[1]), "=r"(r[2]), "=r"(r[3]) : "r"(addr));
}
__device__ __forceinline__ void mma_f16(float* c, const uint32_t* a,
                                        uint32_t b0, uint32_t b1) {
    asm volatile(
        "mma.sync.aligned.m16n8k16.row.col.f32.f16.f16.f32 "
        "{%0,%1,%2,%3}, {%4,%5,%6,%7}, {%8,%9}, {%0,%1,%2,%3};"
        : "+f"(c[0]), "+f"(c[1]), "+f"(c[2]), "+f"(c[3])
        : "r"(a[0]), "r"(a[1]), "r"(a[2]), "r"(a[3]), "r"(b0), "r"(b1));
}

__global__ __launch_bounds__(256, 3)
void gemm_f16_kernel(float* __restrict__ out, int N) {
    extern __shared__ uint32_t smem[];
    const uint32_t sbase = s2u(smem);

    const int tid  = threadIdx.x;
    const int lane = tid & 31;
    const int wid  = tid >> 5;
    const int warp_m = (wid & 3) * 32;
    const int warp_n = (wid >> 2) * 32;
    const int bn = blockIdx.x * BN;
    const int bm = blockIdx.y * BM;

    const int a_row = (lane & 7) + ((lane >> 3) & 1) * 8;
    const int a_k   = (lane >> 4) * 8;
    const int b_row = (lane & 7) + (lane >> 4) * 8;
    const int b_k   = ((lane >> 3) & 1) * 8;

    float acc[2][4][4];
    #pragma unroll
    for (int i = 0; i < 2; i++)
        #pragma unroll
        for (int j = 0; j < 4; j++)
            #pragma unroll
            for (int q = 0; q < 4; q++) acc[i][j][q] = 0.f;

    const int lrow = tid >> 1;
    const int lc   = tid & 1;
    const int arow = bm + lrow;
    const bool avalid = (arow < N);
    const int acl = avalid ? arow : 0;
    const int brow = tid >> 2;
    const int bq   = tid & 3;

    const int T = KTOT / BK;   // 16 tiles

    auto load_tile = [&](int t, int stg) {
        const int kt = t * BK;
        const size_t aoff = (size_t)acl * C + ((kt < C) ? kt : kt - C);
        const __half* gA = (kt < C) ? (g_axh + aoff) : (g_h0h + aoff);
        uint32_t drow = sbase + (stg * STG_W + lrow * LDS_W) * 4;
        #pragma unroll
        for (int c = 0; c < 2; c++) {
            int chunk = lc * 2 + c;
            if (avalid) cp16(drow + chunk * 16, gA + chunk * 8);
            else        cp16z(drow + chunk * 16, gA + chunk * 8);
        }
        const size_t boff = (size_t)(bn + brow) * KTOT + kt + bq * 8;
        uint32_t db = sbase + (stg * STG_W + A_ARR_W + brow * LDS_W) * 4 + bq * 16;
        cp16(db, g_Mth + boff);
        cp_commit();
    };

    load_tile(0, 0);

    for (int t = 0; t < T; t++) {
        cp_wait0();
        __syncthreads();
        if (t + 1 < T) load_tile(t + 1, (t + 1) & 1);

        const int stg = t & 1;
        const uint32_t aS0 = sbase + (stg * STG_W) * 4;
        const uint32_t bS0 = aS0 + A_ARR_W * 4;

        #pragma unroll
        for (int ks = 0; ks < 2; ks++) {
            const int kk = ks * 16;
            uint32_t aR[2][4];
            #pragma unroll
            for (int mt = 0; mt < 2; mt++) {
                uint32_t off = ((warp_m + mt * 16 + a_row) * LDS_W) * 4
                             + (kk + a_k) * 2;
                ldm_x4(aR[mt], aS0 + off);
            }
            #pragma unroll
            for (int ntp = 0; ntp < 2; ntp++) {
                uint32_t bR[4];
                uint32_t off = ((warp_n + ntp * 16 + b_row) * LDS_W) * 4
                             + (kk + b_k) * 2;
                ldm_x4(bR, bS0 + off);
                #pragma unroll
                for (int mt = 0; mt < 2; mt++) {
                    #pragma unroll
                    for (int j = 0; j < 2; j++) {
                        mma_f16(acc[mt][ntp * 2 + j], aR[mt],
                                bR[2 * j], bR[2 * j + 1]);
                    }
                }
            }
        }
        __syncthreads();
    }

    #pragma unroll
    for (int mt = 0; mt < 2; mt++) {
        #pragma unroll
        for (int nt = 0; nt < 4; nt++) {
            int r0  = bm + warp_m + mt * 16 + (lane >> 2);
            int col = bn + warp_n + nt * 8 + (lane & 3) * 2;
            if (r0 < N)
                *reinterpret_cast<float2*>(out + (size_t)r0 * C + col) =
                    make_float2(acc[mt][nt][0], acc[mt][nt][1]);
            int r1 = r0 + 8;
            if (r1 < N)
                *reinterpret_cast<float2*>(out + (size_t)r1 * C + col) =
                    make_float2(acc[mt][nt][2], acc[mt][nt][3]);
        }
    }
}

// ---------------------------------------------------------------------------
// Launch: prep || CSR-build fork (validated in R14), then monolithic
// SpMM -> GEMM (R15's chunked pipeline reverted: L2 contention + tail waves).
// ---------------------------------------------------------------------------
extern "C" void kernel_launch(void* const* d_in, const int* in_sizes, int n_in,
                              void* d_out, int out_size) {
    const float* x    = (const float*)d_in[0];
    const float* vals = (const float*)d_in[1];
    const void*  ei   = d_in[2];
    const float* h0   = (const float*)d_in[3];
    const float* W1   = (const float*)d_in[4];
    const float* W2   = (const float*)d_in[5];
    const float* pa   = (const float*)d_in[6];
    const float* pb   = (const float*)d_in[7];
    float* out = (float*)d_out;

    const int N = in_sizes[0] / C;     // 100000
    int E = in_sizes[1];               // 3200000
    if (E > MAXE) E = MAXE;

    static cudaStream_t s2 = nullptr;
    static cudaEvent_t evFork = nullptr, evJoin = nullptr;
    if (s2 == nullptr) {
        cudaStreamCreateWithFlags(&s2, cudaStreamNonBlocking);
        cudaEventCreateWithFlags(&evFork, cudaEventDisableTiming);
        cudaEventCreateWithFlags(&evJoin, cudaEventDisableTiming);
        cudaFuncSetAttribute(gemm_f16_kernel,
                             cudaFuncAttributeMaxDynamicSharedMemorySize,
                             SMEM_BYTES);
    }

    // fork
    cudaEventRecord(evFork, 0);
    cudaStreamWaitEvent(s2, evFork, 0);

    // side stream: DRAM-streaming prep (independent of edges)
    int total16 = N * C / 16;
    cvt_x_kernel<<<(total16 + 255) / 256, 256, 0, s2>>>(x, total16);
    cvt_h0_kernel<<<(total16 + 255) / 256, 256, 0, s2>>>(h0, total16);
    build_Mt_kernel<<<(C * KTOT + 255) / 256, 256, 0, s2>>>(W1, W2, pa, pb);
    cudaEventRecord(evJoin, s2);

    // main stream: CSR build (latency/atomic-bound, DRAM-idle)
    zero_cnt_kernel<<<(N + 255) / 256, 256>>>(N);
    hist_kernel<<<1563, 256>>>(ei, E, N);
    scan_p1<<<NCH / 256, 256>>>(N);
    scan_p2<<<1, 1024>>>();
    scan_p3<<<NCH / 256, 256>>>(N, E);
    scatter_kernel<<<3125, 256>>>(ei, vals, E, N);

    // join: SpMM needs cvt_x (side) + scatter (main)
    cudaStreamWaitEvent(0, evJoin, 0);
    int spmm_blocks = (N * 32 + 255) / 256;
    spmm_csr_kernel<<<spmm_blocks, 256>>>(N);

    dim3 grid(C / BN, (N + BM - 1) / BM);   // (4, 782)
    gemm_f16_kernel<<<grid, 256, SMEM_BYTES>>>(out, N);
}